// round 13
// baseline (speedup 1.0000x reference)
#include <cuda_runtime.h>
#include <cuda_fp16.h>
#include <cuda_bf16.h>
#include <stdint.h>

#define N_NODES 100000
#define N_EDGES 3200000
#define DIM 128
#define DIM4 32
#define SCAN_NB 98   // ceil(100000/1024)

// ---------------- scratch (device globals) ----------------
__device__ int                g_is64;
__device__ int                g_done;
__device__ volatile int       g_flag;
__device__ unsigned long long g_dh[N_NODES];   // [40,64) = count, [0,40) = deg 2^-24 fixed pt
__device__ float              g_dinv[N_NODES];
__device__ int                g_hist[N_NODES];
__device__ int                g_offs[N_NODES];
__device__ int                g_cursor[N_NODES];
__device__ int2               g_edge[N_EDGES];  // (src row, ew bits)
__device__ int                g_psum[128];
__device__ int                g_poff[128];
__device__ uint4              g_h16[(size_t)N_NODES * 16];  // fp16 h' = dinv*h, 128 halfs/row
__device__ unsigned           g_x16[(size_t)N_NODES * 64];  // layer-1 output (fp16, 128 halfs/row)
__device__ __half             g_w16a[16384];   // W1^T [n][k] fp16, 16B-chunk XOR swizzled (32KB)
__device__ __half             g_w16b[16384];   // W2^T likewise

// ---------------- edge index readers (dtype-agnostic) ----------------
__device__ __forceinline__ int read_row(const void* ei, int E, int i) {
    if (g_is64) return (int)((const long long*)ei)[i];
    return ((const int*)ei)[i];
}
__device__ __forceinline__ int read_col(const void* ei, int E, int i) {
    if (g_is64) return (int)((const long long*)ei)[(size_t)E + i];
    return ((const int*)ei)[(size_t)E + i];
}

__device__ __forceinline__ uint32_t smem_u32(const void* p) {
    uint32_t a;
    asm("{ .reg .u64 t; cvta.to.shared.u64 t, %1; cvt.u32.u64 %0, t; }" : "=r"(a) : "l"(p));
    return a;
}

// ---------------- init: dh = self-loop; flags; dtype detect ----------------
__global__ void init_kernel(const int* ei_words, int n) {
    int i = blockIdx.x * blockDim.x + threadIdx.x;
    if (i < n) g_dh[i] = (1ULL << 24);
    if (i == 0) {
        g_done = 0;
        g_flag = 0;
        int is64 = 1;
        #pragma unroll 1
        for (int k = 0; k < 64; k++)
            if (ei_words[2 * k + 1] != 0) { is64 = 0; break; }
        g_is64 = is64;
    }
}

// ---------------- W prep: W^T [n][k] fp16, 16B chunks XOR-swizzled by (n&7) ----------------
__global__ void wprep_kernel(const float* __restrict__ W1, const float* __restrict__ W2) {
    int idx = blockIdx.x * blockDim.x + threadIdx.x;   // 32768
    int m = idx >> 14;
    int e = idx & 16383;
    int k = e >> 7, nn = e & 127;                       // read W[k][n], n fastest: coalesced
    float v = m ? W2[e] : W1[e];
    int chunk = (k >> 3) ^ (nn & 7);
    int off = nn * 128 + chunk * 8 + (k & 7);           // in fp16 elements
    (m ? g_w16b : g_w16a)[off] = __float2half_rn(v);
}

// ---------------- deg+hist: ONE u64 reduction per edge ----------------
__global__ void deg_hist_kernel(const void* __restrict__ ei,
                                const float* __restrict__ ew, int E, int n) {
    int i = blockIdx.x * blockDim.x + threadIdx.x;
    if (i < E) {
        int c = read_col(ei, E, i);
        if ((unsigned)c >= (unsigned)n) return;
        unsigned long long fx = (unsigned long long)__float2uint_rn(ew[i] * 16777216.0f);
        atomicAdd(&g_dh[c], (1ULL << 40) | fx);   // no return use -> REDG
    }
}

// ================ scan_all: hist/dinv/offs in ONE kernel (co-resident grid) ================
__global__ __launch_bounds__(256) void scan_all(int n, int nb) {
    __shared__ int wsum[8];
    __shared__ int s_last;
    int b = blockIdx.x, tid = threadIdx.x, lane = tid & 31, wid = tid >> 5;
    int base = b * 1024 + tid * 4;

    int v0 = 0, v1 = 0, v2 = 0, v3 = 0;
    #pragma unroll
    for (int j = 0; j < 4; j++) {
        int i = base + j;
        if (i < n) {
            unsigned long long dh = g_dh[i];
            int cnt = (int)(dh >> 40);
            g_hist[i] = cnt;
            float d = (float)(dh & 0xFFFFFFFFFFULL) * (1.0f / 16777216.0f);
            g_dinv[i] = (d > 0.0f) ? rsqrtf(d) : 0.0f;
            if (j == 0) v0 = cnt; else if (j == 1) v1 = cnt;
            else if (j == 2) v2 = cnt; else v3 = cnt;
        }
    }
    int t = v0 + v1 + v2 + v3;

    int incl = t;
    #pragma unroll
    for (int s = 1; s < 32; s <<= 1) {
        int u = __shfl_up_sync(0xffffffffu, incl, s);
        if (lane >= s) incl += u;
    }
    if (lane == 31) wsum[wid] = incl;
    __syncthreads();
    if (tid == 0) {
        int run = 0;
        #pragma unroll
        for (int j = 0; j < 8; j++) { int u = wsum[j]; wsum[j] = run; run += u; }
        g_psum[b] = run;
        __threadfence();
        int ticket = atomicAdd(&g_done, 1);
        s_last = (ticket == nb - 1);
    }
    __syncthreads();

    if (s_last) {
        if (tid < 32) {
            int carry = 0;
            #pragma unroll
            for (int bb = 0; bb < SCAN_NB; bb += 32) {
                int i = bb + tid;
                int v = (i < SCAN_NB) ? ((volatile int*)g_psum)[i] : 0;
                int inc2 = v;
                #pragma unroll
                for (int st = 1; st < 32; st <<= 1) {
                    int u = __shfl_up_sync(0xffffffffu, inc2, st);
                    if (tid >= st) inc2 += u;
                }
                if (i < SCAN_NB) g_poff[i] = carry + inc2 - v;
                carry += __shfl_sync(0xffffffffu, inc2, 31);
            }
        }
        __syncthreads();
        if (tid == 0) { __threadfence(); g_flag = 1; }
    }
    if (tid == 0) { while (g_flag == 0) { } }   // 98 blocks <= 148 SMs: safe spin
    __syncthreads();

    int excl = g_poff[b] + wsum[wid] + incl - t;
    if (base + 0 < n) { g_offs[base + 0] = excl; g_cursor[base + 0] = excl; } excl += v0;
    if (base + 1 < n) { g_offs[base + 1] = excl; g_cursor[base + 1] = excl; } excl += v1;
    if (base + 2 < n) { g_offs[base + 2] = excl; g_cursor[base + 2] = excl; } excl += v2;
    if (base + 3 < n) { g_offs[base + 3] = excl; g_cursor[base + 3] = excl; }
}

// ---------------- scatter: (row, ew) ----------------
__global__ void scatter_kernel(const void* __restrict__ ei,
                               const float* __restrict__ ew, int E, int n) {
    int i = blockIdx.x * blockDim.x + threadIdx.x;
    if (i < E) {
        int r = read_row(ei, E, i);
        int c = read_col(ei, E, i);
        if ((unsigned)r >= (unsigned)n || (unsigned)c >= (unsigned)n) return;
        int pos = atomicAdd(&g_cursor[c], 1);
        if ((unsigned)pos < (unsigned)E)
            g_edge[pos] = make_int2(r, __float_as_int(ew[i]));
    }
}

// ================ tensor-core GEMM: g_h16 = fp16(dinv * (src @ W)) ================
__global__ __launch_bounds__(256) void gemm_mma_kernel(const float* __restrict__ x_ext,
                                                       int layer2, int n) {
    __shared__ __align__(16) __half sB[16384];   // 32KB

    const float* X = x_ext;
    const unsigned* X16 = g_x16;
    const __half* Wimg = layer2 ? g_w16b : g_w16a;

    int tid = threadIdx.x;
    int w = tid >> 5, lane = tid & 31;
    int g = lane >> 2, tg = lane & 3;

    {
        const uint4* src = (const uint4*)Wimg;
        uint4* dst = (uint4*)sB;
        #pragma unroll
        for (int j = 0; j < 8; j++) dst[tid + j * 256] = src[tid + j * 256];
    }
    __syncthreads();
    uint32_t sB_u = smem_u32(sB);

    int r0g = blockIdx.x * 128 + w * 16 + g;
    int r1g = r0g + 8;
    bool v0 = r0g < n, v1 = r1g < n;
    const float* x0 = X + (size_t)(v0 ? r0g : 0) * DIM;
    const float* x1 = X + (size_t)(v1 ? r1g : 0) * DIM;
    const unsigned* q0 = X16 + (size_t)(v0 ? r0g : 0) * 64;
    const unsigned* q1 = X16 + (size_t)(v1 ? r1g : 0) * 64;

    float d[16][4];
    #pragma unroll
    for (int t = 0; t < 16; t++)
        #pragma unroll
        for (int q = 0; q < 4; q++) d[t][q] = 0.0f;

    int half4 = lane >> 3;
    int nrow_lo = (half4 >> 1) * 8 + (lane & 7);
    int cpar = half4 & 1;

    #pragma unroll
    for (int s = 0; s < 8; s++) {
        int k0 = s * 16 + tg * 2;
        uint32_t a0, a1, a2, a3;
        if (layer2) {
            a0 = v0 ? q0[k0 >> 1] : 0u;
            a2 = v0 ? q0[(k0 + 8) >> 1] : 0u;
            a1 = v1 ? q1[k0 >> 1] : 0u;
            a3 = v1 ? q1[(k0 + 8) >> 1] : 0u;
        } else {
            float2 p00 = v0 ? *(const float2*)(x0 + k0)     : make_float2(0.f, 0.f);
            float2 p01 = v0 ? *(const float2*)(x0 + k0 + 8) : make_float2(0.f, 0.f);
            float2 p10 = v1 ? *(const float2*)(x1 + k0)     : make_float2(0.f, 0.f);
            float2 p11 = v1 ? *(const float2*)(x1 + k0 + 8) : make_float2(0.f, 0.f);
            __half2 ah0 = __floats2half2_rn(p00.x, p00.y);
            __half2 ah1 = __floats2half2_rn(p10.x, p10.y);
            __half2 ah2 = __floats2half2_rn(p01.x, p01.y);
            __half2 ah3 = __floats2half2_rn(p11.x, p11.y);
            a0 = *(uint32_t*)&ah0; a1 = *(uint32_t*)&ah1;
            a2 = *(uint32_t*)&ah2; a3 = *(uint32_t*)&ah3;
        }

        int chunk = 2 * s + cpar;
        #pragma unroll
        for (int t = 0; t < 16; t += 2) {
            int nrow = t * 8 + nrow_lo;
            uint32_t addr = sB_u + (uint32_t)nrow * 256
                          + (uint32_t)((chunk ^ (nrow & 7)) << 4);
            uint32_t b0, b1, b2, b3;
            asm volatile("ldmatrix.sync.aligned.m8n8.x4.shared.b16 {%0,%1,%2,%3}, [%4];"
                         : "=r"(b0), "=r"(b1), "=r"(b2), "=r"(b3) : "r"(addr));
            asm volatile("mma.sync.aligned.m16n8k16.row.col.f32.f16.f16.f32 "
                         "{%0,%1,%2,%3}, {%4,%5,%6,%7}, {%8,%9}, {%0,%1,%2,%3};"
                         : "+f"(d[t][0]), "+f"(d[t][1]), "+f"(d[t][2]), "+f"(d[t][3])
                         : "r"(a0), "r"(a1), "r"(a2), "r"(a3), "r"(b0), "r"(b1));
            asm volatile("mma.sync.aligned.m16n8k16.row.col.f32.f16.f16.f32 "
                         "{%0,%1,%2,%3}, {%4,%5,%6,%7}, {%8,%9}, {%0,%1,%2,%3};"
                         : "+f"(d[t+1][0]), "+f"(d[t+1][1]), "+f"(d[t+1][2]), "+f"(d[t+1][3])
                         : "r"(a0), "r"(a1), "r"(a2), "r"(a3), "r"(b2), "r"(b3));
        }
    }

    float di0 = v0 ? g_dinv[r0g] : 0.0f;
    float di1 = v1 ? g_dinv[r1g] : 0.0f;
    unsigned* H0 = (unsigned*)g_h16 + (size_t)(v0 ? r0g : 0) * 64;
    unsigned* H1 = (unsigned*)g_h16 + (size_t)(v1 ? r1g : 0) * 64;
    #pragma unroll
    for (int t = 0; t < 16; t++) {
        int cw = t * 4 + tg;
        if (v0) {
            __half2 o = __floats2half2_rn(di0 * d[t][0], di0 * d[t][1]);
            H0[cw] = *(unsigned*)&o;
        }
        if (v1) {
            __half2 o = __floats2half2_rn(di1 * d[t][2], di1 * d[t][3]);
            H1[cw] = *(unsigned*)&o;
        }
    }
}

// ---------------- pull aggregation: one warp per node, 4 edges/iter x 8 lanes ----------------
__global__ __launch_bounds__(256) void agg_kernel(const float* __restrict__ bias,
                                                  float* __restrict__ out_ext,
                                                  int n, int do_relu, int dst_is_x2) {
    int gw = (blockIdx.x * blockDim.x + threadIdx.x) >> 5;
    int lane = threadIdx.x & 31;
    if (gw >= n) return;
    int i = gw;
    int q  = lane >> 3;      // which of 4 concurrent edges
    int l8 = lane & 7;       // 32B segment (16 cols) of the 256B fp16 row

    int off = g_offs[i];
    int end = off + g_hist[i];

    float acc[16];
    #pragma unroll
    for (int j = 0; j < 16; j++) acc[j] = 0.0f;

    #pragma unroll 2
    for (int e0 = off; e0 < end; e0 += 4) {
        int e = e0 + q;
        if (e < end) {
            int2 ed = g_edge[e];
            float c = __int_as_float(ed.y);
            const uint4* row = g_h16 + (size_t)ed.x * 16 + l8 * 2;
            uint4 va = row[0];
            uint4 vb = row[1];
            __half2* ha = (__half2*)&va;
            __half2* hb = (__half2*)&vb;
            #pragma unroll
            for (int p = 0; p < 4; p++) {
                float2 fa = __half22float2(ha[p]);
                float2 fb = __half22float2(hb[p]);
                acc[2 * p + 0] += c * fa.x;
                acc[2 * p + 1] += c * fa.y;
                acc[8 + 2 * p + 0] += c * fb.x;
                acc[8 + 2 * p + 1] += c * fb.y;
            }
        }
    }
    #pragma unroll
    for (int j = 0; j < 16; j++) {
        acc[j] += __shfl_xor_sync(0xffffffffu, acc[j], 8);
        acc[j] += __shfl_xor_sync(0xffffffffu, acc[j], 16);
    }

    // this lane outputs cols [l8*16 + q*4, +4)
    float di = g_dinv[i];
    uint4 sv = g_h16[(size_t)i * 16 + l8 * 2 + (q >> 1)];
    __half2* sh = (__half2*)&sv;
    float2 s0 = __half22float2(sh[(q & 1) * 2 + 0]);
    float2 s1 = __half22float2(sh[(q & 1) * 2 + 1]);
    float4 b4 = ((const float4*)bias)[l8 * 4 + q];

    float4 r;
    r.x = di * (acc[q * 4 + 0] + s0.x) + b4.x;
    r.y = di * (acc[q * 4 + 1] + s0.y) + b4.y;
    r.z = di * (acc[q * 4 + 2] + s1.x) + b4.z;
    r.w = di * (acc[q * 4 + 3] + s1.y) + b4.w;
    if (do_relu) {
        r.x = fmaxf(r.x, 0.f); r.y = fmaxf(r.y, 0.f);
        r.z = fmaxf(r.z, 0.f); r.w = fmaxf(r.w, 0.f);
    }
    if (dst_is_x2) {
        __half2 o0 = __floats2half2_rn(r.x, r.y);
        __half2 o1 = __floats2half2_rn(r.z, r.w);
        uint2 o; o.x = *(unsigned*)&o0; o.y = *(unsigned*)&o1;
        ((uint2*)g_x16)[(size_t)i * 32 + l8 * 4 + q] = o;
    } else {
        ((float4*)out_ext)[(size_t)i * 32 + l8 * 4 + q] = r;
    }
}

// ---------------- launch (kernel launches ONLY — graph-capturable) ----------------
extern "C" void kernel_launch(void* const* d_in, const int* in_sizes, int n_in,
                              void* d_out, int out_size) {
    const float* x  = (const float*)d_in[0];
    const void*  ei = d_in[1];                 // [2, E], int32 OR int64
    const float* ew = (const float*)d_in[2];
    const float* W1 = (const float*)d_in[3];
    const float* b1 = (const float*)d_in[4];
    const float* W2 = (const float*)d_in[5];
    const float* b2 = (const float*)d_in[6];
    float* out = (float*)d_out;

    int n = in_sizes[0] / DIM;   // 100000
    int E = in_sizes[2];         // 3200000

    int nb_n  = (n + 255) / 256;
    int nb_e  = (E + 511) / 512;
    int nb_wn = (n * 32 + 255) / 256;  // one warp per node
    int nb_t  = (n + 127) / 128;       // 782 gemm tiles
    int nb_s  = (n + 1023) / 1024;     // 98

    // preprocessing: CSR-ize edges by destination; W fp16 images
    init_kernel<<<nb_n, 256>>>((const int*)ei, n);
    wprep_kernel<<<128, 256>>>(W1, W2);
    deg_hist_kernel<<<nb_e, 512>>>(ei, ew, E, n);
    scan_all<<<nb_s, 256>>>(n, nb_s);
    scatter_kernel<<<nb_e, 512>>>(ei, ew, E, n);

    // layer 1: g_h16 = fp16(dinv * (x @ W1)) ; g_x16 = fp16(agg + b1, relu)
    gemm_mma_kernel<<<nb_t, 256>>>(x, /*layer2=*/0, n);
    agg_kernel<<<nb_wn, 256>>>(b1, out, n, /*relu=*/1, /*dst_is_x2=*/1);

    // layer 2: g_h16 = fp16(dinv * (g_x16 @ W2)) ; out = agg + b2
    gemm_mma_kernel<<<nb_t, 256>>>(x, /*layer2=*/1, n);
    agg_kernel<<<nb_wn, 256>>>(b2, out, n, /*relu=*/0, /*dst_is_x2=*/0);
}

// round 14
// speedup vs baseline: 1.3316x; 1.3316x over previous
#include <cuda_runtime.h>
#include <cuda_fp16.h>
#include <cuda_bf16.h>
#include <stdint.h>

#define N_NODES 100000
#define N_EDGES 3200000
#define DIM 128
#define DIM4 32
#define SCAN_NB 98   // ceil(100000/1024)

// ---------------- scratch (device globals) ----------------
__device__ int                g_is64;
__device__ int                g_done;
__device__ volatile int       g_flag;
__device__ unsigned long long g_dh[N_NODES];   // [40,64) = count, [0,40) = deg 2^-24 fixed pt
__device__ float              g_dinv[N_NODES];
__device__ int                g_hist[N_NODES];
__device__ int                g_offs[N_NODES];
__device__ int                g_cursor[N_NODES];
__device__ int2               g_edge[N_EDGES];  // (src row, ew bits)
__device__ int                g_psum[128];
__device__ int                g_poff[128];
__device__ uint4              g_h16[(size_t)N_NODES * 16];  // fp16 h' = dinv*h, 128 halfs/row
__device__ unsigned           g_x16[(size_t)N_NODES * 64];  // layer-1 output (fp16, 128 halfs/row)
__device__ __half             g_w16a[16384];   // W1^T [n][k] fp16, 16B-chunk XOR swizzled (32KB)
__device__ __half             g_w16b[16384];   // W2^T likewise

// ---------------- edge index readers (dtype-agnostic) ----------------
__device__ __forceinline__ int read_row(const void* ei, int E, int i) {
    if (g_is64) return (int)((const long long*)ei)[i];
    return ((const int*)ei)[i];
}
__device__ __forceinline__ int read_col(const void* ei, int E, int i) {
    if (g_is64) return (int)((const long long*)ei)[(size_t)E + i];
    return ((const int*)ei)[(size_t)E + i];
}

__device__ __forceinline__ uint32_t smem_u32(const void* p) {
    uint32_t a;
    asm("{ .reg .u64 t; cvta.to.shared.u64 t, %1; cvt.u32.u64 %0, t; }" : "=r"(a) : "l"(p));
    return a;
}

// ---------------- init: dh = self-loop; flags; dtype detect ----------------
__global__ void init_kernel(const int* ei_words, int n) {
    int i = blockIdx.x * blockDim.x + threadIdx.x;
    if (i < n) g_dh[i] = (1ULL << 24);
    if (i == 0) {
        g_done = 0;
        g_flag = 0;
        int is64 = 1;
        #pragma unroll 1
        for (int k = 0; k < 64; k++)
            if (ei_words[2 * k + 1] != 0) { is64 = 0; break; }
        g_is64 = is64;
    }
}

// ---------------- W prep: W^T [n][k] fp16, 16B chunks XOR-swizzled by (n&7) ----------------
__global__ void wprep_kernel(const float* __restrict__ W1, const float* __restrict__ W2) {
    int idx = blockIdx.x * blockDim.x + threadIdx.x;   // 32768
    int m = idx >> 14;
    int e = idx & 16383;
    int k = e >> 7, nn = e & 127;                       // read W[k][n], n fastest: coalesced
    float v = m ? W2[e] : W1[e];
    int chunk = (k >> 3) ^ (nn & 7);
    int off = nn * 128 + chunk * 8 + (k & 7);           // in fp16 elements
    (m ? g_w16b : g_w16a)[off] = __float2half_rn(v);
}

// ---------------- deg+hist: ONE u64 reduction per edge ----------------
__global__ void deg_hist_kernel(const void* __restrict__ ei,
                                const float* __restrict__ ew, int E, int n) {
    int i = blockIdx.x * blockDim.x + threadIdx.x;
    if (i < E) {
        int c = read_col(ei, E, i);
        if ((unsigned)c >= (unsigned)n) return;
        unsigned long long fx = (unsigned long long)__float2uint_rn(ew[i] * 16777216.0f);
        atomicAdd(&g_dh[c], (1ULL << 40) | fx);   // no return use -> REDG
    }
}

// ================ scan_all: hist/dinv/offs in ONE kernel (co-resident grid) ================
__global__ __launch_bounds__(256) void scan_all(int n, int nb) {
    __shared__ int wsum[8];
    __shared__ int s_last;
    int b = blockIdx.x, tid = threadIdx.x, lane = tid & 31, wid = tid >> 5;
    int base = b * 1024 + tid * 4;

    int v0 = 0, v1 = 0, v2 = 0, v3 = 0;
    #pragma unroll
    for (int j = 0; j < 4; j++) {
        int i = base + j;
        if (i < n) {
            unsigned long long dh = g_dh[i];
            int cnt = (int)(dh >> 40);
            g_hist[i] = cnt;
            float d = (float)(dh & 0xFFFFFFFFFFULL) * (1.0f / 16777216.0f);
            g_dinv[i] = (d > 0.0f) ? rsqrtf(d) : 0.0f;
            if (j == 0) v0 = cnt; else if (j == 1) v1 = cnt;
            else if (j == 2) v2 = cnt; else v3 = cnt;
        }
    }
    int t = v0 + v1 + v2 + v3;

    int incl = t;
    #pragma unroll
    for (int s = 1; s < 32; s <<= 1) {
        int u = __shfl_up_sync(0xffffffffu, incl, s);
        if (lane >= s) incl += u;
    }
    if (lane == 31) wsum[wid] = incl;
    __syncthreads();
    if (tid == 0) {
        int run = 0;
        #pragma unroll
        for (int j = 0; j < 8; j++) { int u = wsum[j]; wsum[j] = run; run += u; }
        g_psum[b] = run;
        __threadfence();
        int ticket = atomicAdd(&g_done, 1);
        s_last = (ticket == nb - 1);
    }
    __syncthreads();

    if (s_last) {
        if (tid < 32) {
            int carry = 0;
            #pragma unroll
            for (int bb = 0; bb < SCAN_NB; bb += 32) {
                int i = bb + tid;
                int v = (i < SCAN_NB) ? ((volatile int*)g_psum)[i] : 0;
                int inc2 = v;
                #pragma unroll
                for (int st = 1; st < 32; st <<= 1) {
                    int u = __shfl_up_sync(0xffffffffu, inc2, st);
                    if (tid >= st) inc2 += u;
                }
                if (i < SCAN_NB) g_poff[i] = carry + inc2 - v;
                carry += __shfl_sync(0xffffffffu, inc2, 31);
            }
        }
        __syncthreads();
        if (tid == 0) { __threadfence(); g_flag = 1; }
    }
    if (tid == 0) { while (g_flag == 0) { } }   // 98 blocks <= 148 SMs: safe spin
    __syncthreads();

    int excl = g_poff[b] + wsum[wid] + incl - t;
    if (base + 0 < n) { g_offs[base + 0] = excl; g_cursor[base + 0] = excl; } excl += v0;
    if (base + 1 < n) { g_offs[base + 1] = excl; g_cursor[base + 1] = excl; } excl += v1;
    if (base + 2 < n) { g_offs[base + 2] = excl; g_cursor[base + 2] = excl; } excl += v2;
    if (base + 3 < n) { g_offs[base + 3] = excl; g_cursor[base + 3] = excl; }
}

// ---------------- scatter: (row, ew) ----------------
__global__ void scatter_kernel(const void* __restrict__ ei,
                               const float* __restrict__ ew, int E, int n) {
    int i = blockIdx.x * blockDim.x + threadIdx.x;
    if (i < E) {
        int r = read_row(ei, E, i);
        int c = read_col(ei, E, i);
        if ((unsigned)r >= (unsigned)n || (unsigned)c >= (unsigned)n) return;
        int pos = atomicAdd(&g_cursor[c], 1);
        if ((unsigned)pos < (unsigned)E)
            g_edge[pos] = make_int2(r, __float_as_int(ew[i]));
    }
}

// ================ tensor-core GEMM: g_h16 = fp16(dinv * (src @ W)) ================
// block = 256 thr (8 warps x 16 rows = 128-row tile); B = W^T[n][k] fp16 in smem (swizzled)
// layer1: A from fp32 x (cvt); layer2: A direct from fp16 g_x16
__global__ __launch_bounds__(256) void gemm_mma_kernel(const float* __restrict__ x_ext,
                                                       int layer2, int n) {
    __shared__ __align__(16) __half sB[16384];   // 32KB

    const float* X = x_ext;
    const unsigned* X16 = g_x16;
    const __half* Wimg = layer2 ? g_w16b : g_w16a;

    int tid = threadIdx.x;
    int w = tid >> 5, lane = tid & 31;
    int g = lane >> 2, tg = lane & 3;

    {
        const uint4* src = (const uint4*)Wimg;
        uint4* dst = (uint4*)sB;
        #pragma unroll
        for (int j = 0; j < 8; j++) dst[tid + j * 256] = src[tid + j * 256];
    }
    __syncthreads();
    uint32_t sB_u = smem_u32(sB);

    int r0g = blockIdx.x * 128 + w * 16 + g;
    int r1g = r0g + 8;
    bool v0 = r0g < n, v1 = r1g < n;
    const float* x0 = X + (size_t)(v0 ? r0g : 0) * DIM;
    const float* x1 = X + (size_t)(v1 ? r1g : 0) * DIM;
    const unsigned* q0 = X16 + (size_t)(v0 ? r0g : 0) * 64;
    const unsigned* q1 = X16 + (size_t)(v1 ? r1g : 0) * 64;

    float d[16][4];
    #pragma unroll
    for (int t = 0; t < 16; t++)
        #pragma unroll
        for (int q = 0; q < 4; q++) d[t][q] = 0.0f;

    int half4 = lane >> 3;
    int nrow_lo = (half4 >> 1) * 8 + (lane & 7);
    int cpar = half4 & 1;

    #pragma unroll
    for (int s = 0; s < 8; s++) {
        int k0 = s * 16 + tg * 2;
        uint32_t a0, a1, a2, a3;
        if (layer2) {
            a0 = v0 ? q0[k0 >> 1] : 0u;
            a2 = v0 ? q0[(k0 + 8) >> 1] : 0u;
            a1 = v1 ? q1[k0 >> 1] : 0u;
            a3 = v1 ? q1[(k0 + 8) >> 1] : 0u;
        } else {
            float2 p00 = v0 ? *(const float2*)(x0 + k0)     : make_float2(0.f, 0.f);
            float2 p01 = v0 ? *(const float2*)(x0 + k0 + 8) : make_float2(0.f, 0.f);
            float2 p10 = v1 ? *(const float2*)(x1 + k0)     : make_float2(0.f, 0.f);
            float2 p11 = v1 ? *(const float2*)(x1 + k0 + 8) : make_float2(0.f, 0.f);
            __half2 ah0 = __floats2half2_rn(p00.x, p00.y);
            __half2 ah1 = __floats2half2_rn(p10.x, p10.y);
            __half2 ah2 = __floats2half2_rn(p01.x, p01.y);
            __half2 ah3 = __floats2half2_rn(p11.x, p11.y);
            a0 = *(uint32_t*)&ah0; a1 = *(uint32_t*)&ah1;
            a2 = *(uint32_t*)&ah2; a3 = *(uint32_t*)&ah3;
        }

        int chunk = 2 * s + cpar;
        #pragma unroll
        for (int t = 0; t < 16; t += 2) {
            int nrow = t * 8 + nrow_lo;
            uint32_t addr = sB_u + (uint32_t)nrow * 256
                          + (uint32_t)((chunk ^ (nrow & 7)) << 4);
            uint32_t b0, b1, b2, b3;
            asm volatile("ldmatrix.sync.aligned.m8n8.x4.shared.b16 {%0,%1,%2,%3}, [%4];"
                         : "=r"(b0), "=r"(b1), "=r"(b2), "=r"(b3) : "r"(addr));
            asm volatile("mma.sync.aligned.m16n8k16.row.col.f32.f16.f16.f32 "
                         "{%0,%1,%2,%3}, {%4,%5,%6,%7}, {%8,%9}, {%0,%1,%2,%3};"
                         : "+f"(d[t][0]), "+f"(d[t][1]), "+f"(d[t][2]), "+f"(d[t][3])
                         : "r"(a0), "r"(a1), "r"(a2), "r"(a3), "r"(b0), "r"(b1));
            asm volatile("mma.sync.aligned.m16n8k16.row.col.f32.f16.f16.f32 "
                         "{%0,%1,%2,%3}, {%4,%5,%6,%7}, {%8,%9}, {%0,%1,%2,%3};"
                         : "+f"(d[t+1][0]), "+f"(d[t+1][1]), "+f"(d[t+1][2]), "+f"(d[t+1][3])
                         : "r"(a0), "r"(a1), "r"(a2), "r"(a3), "r"(b2), "r"(b3));
        }
    }

    float di0 = v0 ? g_dinv[r0g] : 0.0f;
    float di1 = v1 ? g_dinv[r1g] : 0.0f;
    unsigned* H0 = (unsigned*)g_h16 + (size_t)(v0 ? r0g : 0) * 64;
    unsigned* H1 = (unsigned*)g_h16 + (size_t)(v1 ? r1g : 0) * 64;
    #pragma unroll
    for (int t = 0; t < 16; t++) {
        int cw = t * 4 + tg;
        if (v0) {
            __half2 o = __floats2half2_rn(di0 * d[t][0], di0 * d[t][1]);
            H0[cw] = *(unsigned*)&o;
        }
        if (v1) {
            __half2 o = __floats2half2_rn(di1 * d[t][2], di1 * d[t][3]);
            H1[cw] = *(unsigned*)&o;
        }
    }
}

// ---------------- pull aggregation (R12-proven): one warp/node, 2 edges x 16 lanes ----------------
// out[i] = dinv[i] * ( sum_e ew_e * h'[src_e] + h'[i] ) + b ; relu opt; fp16 dst for x16
__global__ __launch_bounds__(256) void agg_kernel(const float* __restrict__ bias,
                                                  float* __restrict__ out_ext,
                                                  int n, int do_relu, int dst_is_x2) {
    int gw = (blockIdx.x * blockDim.x + threadIdx.x) >> 5;
    int lane = threadIdx.x & 31;
    if (gw >= n) return;
    int i = gw;
    int half = lane >> 4;    // which of 2 concurrent edges
    int li = lane & 15;      // 16B chunk within the 256B fp16 row

    int off = g_offs[i];
    int end = off + g_hist[i];

    float acc[8];
    #pragma unroll
    for (int j = 0; j < 8; j++) acc[j] = 0.0f;

    #pragma unroll 4
    for (int e0 = off; e0 < end; e0 += 2) {
        int e = e0 + half;
        if (e < end) {
            int2 ed = g_edge[e];
            float c = __int_as_float(ed.y);
            uint4 v = g_h16[(size_t)ed.x * 16 + li];
            __half2* hp = (__half2*)&v;
            float2 f0 = __half22float2(hp[0]);
            float2 f1 = __half22float2(hp[1]);
            float2 f2 = __half22float2(hp[2]);
            float2 f3 = __half22float2(hp[3]);
            acc[0] += c * f0.x; acc[1] += c * f0.y;
            acc[2] += c * f1.x; acc[3] += c * f1.y;
            acc[4] += c * f2.x; acc[5] += c * f2.y;
            acc[6] += c * f3.x; acc[7] += c * f3.y;
        }
    }
    #pragma unroll
    for (int j = 0; j < 8; j++)
        acc[j] += __shfl_xor_sync(0xffffffffu, acc[j], 16);

    float di = g_dinv[i];
    uint4 sv = g_h16[(size_t)i * 16 + li];
    __half2* sh = (__half2*)&sv;
    float2 s0 = __half22float2(sh[2 * half + 0]);
    float2 s1 = __half22float2(sh[2 * half + 1]);
    float4 b4 = ((const float4*)bias)[li * 2 + half];

    float4 r;
    r.x = di * (acc[4 * half + 0] + s0.x) + b4.x;
    r.y = di * (acc[4 * half + 1] + s0.y) + b4.y;
    r.z = di * (acc[4 * half + 2] + s1.x) + b4.z;
    r.w = di * (acc[4 * half + 3] + s1.y) + b4.w;
    if (do_relu) {
        r.x = fmaxf(r.x, 0.f); r.y = fmaxf(r.y, 0.f);
        r.z = fmaxf(r.z, 0.f); r.w = fmaxf(r.w, 0.f);
    }
    if (dst_is_x2) {
        __half2 o0 = __floats2half2_rn(r.x, r.y);
        __half2 o1 = __floats2half2_rn(r.z, r.w);
        uint2 o; o.x = *(unsigned*)&o0; o.y = *(unsigned*)&o1;
        ((uint2*)g_x16)[(size_t)i * 32 + li * 2 + half] = o;
    } else {
        ((float4*)out_ext)[(size_t)i * 32 + li * 2 + half] = r;
    }
}

// ---------------- launch (kernel launches ONLY — graph-capturable) ----------------
extern "C" void kernel_launch(void* const* d_in, const int* in_sizes, int n_in,
                              void* d_out, int out_size) {
    const float* x  = (const float*)d_in[0];
    const void*  ei = d_in[1];                 // [2, E], int32 OR int64
    const float* ew = (const float*)d_in[2];
    const float* W1 = (const float*)d_in[3];
    const float* b1 = (const float*)d_in[4];
    const float* W2 = (const float*)d_in[5];
    const float* b2 = (const float*)d_in[6];
    float* out = (float*)d_out;

    int n = in_sizes[0] / DIM;   // 100000
    int E = in_sizes[2];         // 3200000

    int nb_n  = (n + 255) / 256;
    int nb_e  = (E + 511) / 512;
    int nb_wn = (n * 32 + 255) / 256;  // one warp per node
    int nb_t  = (n + 127) / 128;       // 782 gemm tiles
    int nb_s  = (n + 1023) / 1024;     // 98

    // preprocessing: CSR-ize edges by destination; W fp16 images
    init_kernel<<<nb_n, 256>>>((const int*)ei, n);
    wprep_kernel<<<128, 256>>>(W1, W2);
    deg_hist_kernel<<<nb_e, 512>>>(ei, ew, E, n);
    scan_all<<<nb_s, 256>>>(n, nb_s);
    scatter_kernel<<<nb_e, 512>>>(ei, ew, E, n);

    // layer 1: g_h16 = fp16(dinv * (x @ W1)) ; g_x16 = fp16(agg + b1, relu)
    gemm_mma_kernel<<<nb_t, 256>>>(x, /*layer2=*/0, n);
    agg_kernel<<<nb_wn, 256>>>(b1, out, n, /*relu=*/1, /*dst_is_x2=*/1);

    // layer 2: g_h16 = fp16(dinv * (g_x16 @ W2)) ; out = agg + b2
    gemm_mma_kernel<<<nb_t, 256>>>(x, /*layer2=*/1, n);
    agg_kernel<<<nb_wn, 256>>>(b2, out, n, /*relu=*/0, /*dst_is_x2=*/0);
}

// round 15
// speedup vs baseline: 1.3370x; 1.0041x over previous
#include <cuda_runtime.h>
#include <cuda_fp16.h>
#include <cuda_bf16.h>
#include <stdint.h>

#define N_NODES 100000
#define N_EDGES 3200000
#define DIM 128
#define DIM4 32
#define SCAN_NB 98   // ceil(100000/1024)

// ---------------- scratch (device globals) ----------------
__device__ int                g_is64;
__device__ int                g_done;
__device__ volatile int       g_flag;
__device__ unsigned long long g_dh[N_NODES];   // [40,64) = count, [0,40) = deg 2^-24 fixed pt
__device__ float              g_dinv[N_NODES];
__device__ int                g_hist[N_NODES];
__device__ int                g_offs[N_NODES];
__device__ int                g_cursor[N_NODES];
__device__ int2               g_edge[N_EDGES];  // (src row, (ew*dinv[src]) bits)
__device__ int                g_psum[128];
__device__ int                g_poff[128];
__device__ uint4              g_h16[(size_t)N_NODES * 16];  // fp16 raw h = src @ W, 128 halfs/row
__device__ unsigned           g_x16[(size_t)N_NODES * 64];  // layer-1 output (fp16)
__device__ __half             g_w16a[16384];   // W1^T [n][k] fp16, 16B-chunk XOR swizzled (32KB)
__device__ __half             g_w16b[16384];   // W2^T likewise

// ---------------- edge index readers (dtype-agnostic) ----------------
__device__ __forceinline__ int read_row(const void* ei, int E, int i) {
    if (g_is64) return (int)((const long long*)ei)[i];
    return ((const int*)ei)[i];
}
__device__ __forceinline__ int read_col(const void* ei, int E, int i) {
    if (g_is64) return (int)((const long long*)ei)[(size_t)E + i];
    return ((const int*)ei)[(size_t)E + i];
}

__device__ __forceinline__ uint32_t smem_u32(const void* p) {
    uint32_t a;
    asm("{ .reg .u64 t; cvta.to.shared.u64 t, %1; cvt.u32.u64 %0, t; }" : "=r"(a) : "l"(p));
    return a;
}

// ---------------- init: dh = self-loop; flags; dtype detect ----------------
__global__ void init_kernel(const int* ei_words, int n) {
    int i = blockIdx.x * blockDim.x + threadIdx.x;
    if (i < n) g_dh[i] = (1ULL << 24);
    if (i == 0) {
        g_done = 0;
        g_flag = 0;
        int is64 = 1;
        #pragma unroll 1
        for (int k = 0; k < 64; k++)
            if (ei_words[2 * k + 1] != 0) { is64 = 0; break; }
        g_is64 = is64;
    }
}

// ---------------- W prep: W^T [n][k] fp16, 16B chunks XOR-swizzled by (n&7) ----------------
__global__ void wprep_kernel(const float* __restrict__ W1, const float* __restrict__ W2) {
    int idx = blockIdx.x * blockDim.x + threadIdx.x;   // 32768
    int m = idx >> 14;
    int e = idx & 16383;
    int k = e >> 7, nn = e & 127;                       // read W[k][n], n fastest: coalesced
    float v = m ? W2[e] : W1[e];
    int chunk = (k >> 3) ^ (nn & 7);
    int off = nn * 128 + chunk * 8 + (k & 7);           // in fp16 elements
    (m ? g_w16b : g_w16a)[off] = __float2half_rn(v);
}

// ---------------- deg+hist: ONE u64 reduction per edge ----------------
__global__ void deg_hist_kernel(const void* __restrict__ ei,
                                const float* __restrict__ ew, int E, int n) {
    int i = blockIdx.x * blockDim.x + threadIdx.x;
    if (i < E) {
        int c = read_col(ei, E, i);
        if ((unsigned)c >= (unsigned)n) return;
        unsigned long long fx = (unsigned long long)__float2uint_rn(ew[i] * 16777216.0f);
        atomicAdd(&g_dh[c], (1ULL << 40) | fx);   // no return use -> REDG
    }
}

// ================ scan_all: hist/dinv/offs in ONE kernel (co-resident grid) ================
__global__ __launch_bounds__(256) void scan_all(int n, int nb) {
    __shared__ int wsum[8];
    __shared__ int s_last;
    int b = blockIdx.x, tid = threadIdx.x, lane = tid & 31, wid = tid >> 5;
    int base = b * 1024 + tid * 4;

    int v0 = 0, v1 = 0, v2 = 0, v3 = 0;
    #pragma unroll
    for (int j = 0; j < 4; j++) {
        int i = base + j;
        if (i < n) {
            unsigned long long dh = g_dh[i];
            int cnt = (int)(dh >> 40);
            g_hist[i] = cnt;
            float d = (float)(dh & 0xFFFFFFFFFFULL) * (1.0f / 16777216.0f);
            g_dinv[i] = (d > 0.0f) ? rsqrtf(d) : 0.0f;
            if (j == 0) v0 = cnt; else if (j == 1) v1 = cnt;
            else if (j == 2) v2 = cnt; else v3 = cnt;
        }
    }
    int t = v0 + v1 + v2 + v3;

    int incl = t;
    #pragma unroll
    for (int s = 1; s < 32; s <<= 1) {
        int u = __shfl_up_sync(0xffffffffu, incl, s);
        if (lane >= s) incl += u;
    }
    if (lane == 31) wsum[wid] = incl;
    __syncthreads();
    if (tid == 0) {
        int run = 0;
        #pragma unroll
        for (int j = 0; j < 8; j++) { int u = wsum[j]; wsum[j] = run; run += u; }
        g_psum[b] = run;
        __threadfence();
        int ticket = atomicAdd(&g_done, 1);
        s_last = (ticket == nb - 1);
    }
    __syncthreads();

    if (s_last) {
        if (tid < 32) {
            int carry = 0;
            #pragma unroll
            for (int bb = 0; bb < SCAN_NB; bb += 32) {
                int i = bb + tid;
                int v = (i < SCAN_NB) ? ((volatile int*)g_psum)[i] : 0;
                int inc2 = v;
                #pragma unroll
                for (int st = 1; st < 32; st <<= 1) {
                    int u = __shfl_up_sync(0xffffffffu, inc2, st);
                    if (tid >= st) inc2 += u;
                }
                if (i < SCAN_NB) g_poff[i] = carry + inc2 - v;
                carry += __shfl_sync(0xffffffffu, inc2, 31);
            }
        }
        __syncthreads();
        if (tid == 0) { __threadfence(); g_flag = 1; }
    }
    if (tid == 0) { while (g_flag == 0) { } }   // 98 blocks <= 148 SMs: safe spin
    __syncthreads();

    int excl = g_poff[b] + wsum[wid] + incl - t;
    if (base + 0 < n) { g_offs[base + 0] = excl; g_cursor[base + 0] = excl; } excl += v0;
    if (base + 1 < n) { g_offs[base + 1] = excl; g_cursor[base + 1] = excl; } excl += v1;
    if (base + 2 < n) { g_offs[base + 2] = excl; g_cursor[base + 2] = excl; } excl += v2;
    if (base + 3 < n) { g_offs[base + 3] = excl; g_cursor[base + 3] = excl; }
}

// ---------------- scatter: (row, ew * dinv[row]) ----------------
__global__ void scatter_kernel(const void* __restrict__ ei,
                               const float* __restrict__ ew, int E, int n) {
    int i = blockIdx.x * blockDim.x + threadIdx.x;
    if (i < E) {
        int r = read_row(ei, E, i);
        int c = read_col(ei, E, i);
        if ((unsigned)r >= (unsigned)n || (unsigned)c >= (unsigned)n) return;
        int pos = atomicAdd(&g_cursor[c], 1);
        if ((unsigned)pos < (unsigned)E)
            g_edge[pos] = make_int2(r, __float_as_int(ew[i] * g_dinv[r]));
    }
}

// ================ tensor-core GEMM: g_h16 = fp16(src @ W)  (NO dinv — stream-independent) ======
// block = 256 thr (8 warps x 16 rows = 128-row tile); B = W^T[n][k] fp16 in smem (swizzled)
__global__ __launch_bounds__(256) void gemm_mma_kernel(const float* __restrict__ x_ext,
                                                       int layer2, int n) {
    __shared__ __align__(16) __half sB[16384];   // 32KB

    const float* X = x_ext;
    const unsigned* X16 = g_x16;
    const __half* Wimg = layer2 ? g_w16b : g_w16a;

    int tid = threadIdx.x;
    int w = tid >> 5, lane = tid & 31;
    int g = lane >> 2, tg = lane & 3;

    {
        const uint4* src = (const uint4*)Wimg;
        uint4* dst = (uint4*)sB;
        #pragma unroll
        for (int j = 0; j < 8; j++) dst[tid + j * 256] = src[tid + j * 256];
    }
    __syncthreads();
    uint32_t sB_u = smem_u32(sB);

    int r0g = blockIdx.x * 128 + w * 16 + g;
    int r1g = r0g + 8;
    bool v0 = r0g < n, v1 = r1g < n;
    const float* x0 = X + (size_t)(v0 ? r0g : 0) * DIM;
    const float* x1 = X + (size_t)(v1 ? r1g : 0) * DIM;
    const unsigned* q0 = X16 + (size_t)(v0 ? r0g : 0) * 64;
    const unsigned* q1 = X16 + (size_t)(v1 ? r1g : 0) * 64;

    float d[16][4];
    #pragma unroll
    for (int t = 0; t < 16; t++)
        #pragma unroll
        for (int q = 0; q < 4; q++) d[t][q] = 0.0f;

    int half4 = lane >> 3;
    int nrow_lo = (half4 >> 1) * 8 + (lane & 7);
    int cpar = half4 & 1;

    #pragma unroll
    for (int s = 0; s < 8; s++) {
        int k0 = s * 16 + tg * 2;
        uint32_t a0, a1, a2, a3;
        if (layer2) {
            a0 = v0 ? q0[k0 >> 1] : 0u;
            a2 = v0 ? q0[(k0 + 8) >> 1] : 0u;
            a1 = v1 ? q1[k0 >> 1] : 0u;
            a3 = v1 ? q1[(k0 + 8) >> 1] : 0u;
        } else {
            float2 p00 = v0 ? *(const float2*)(x0 + k0)     : make_float2(0.f, 0.f);
            float2 p01 = v0 ? *(const float2*)(x0 + k0 + 8) : make_float2(0.f, 0.f);
            float2 p10 = v1 ? *(const float2*)(x1 + k0)     : make_float2(0.f, 0.f);
            float2 p11 = v1 ? *(const float2*)(x1 + k0 + 8) : make_float2(0.f, 0.f);
            __half2 ah0 = __floats2half2_rn(p00.x, p00.y);
            __half2 ah1 = __floats2half2_rn(p10.x, p10.y);
            __half2 ah2 = __floats2half2_rn(p01.x, p01.y);
            __half2 ah3 = __floats2half2_rn(p11.x, p11.y);
            a0 = *(uint32_t*)&ah0; a1 = *(uint32_t*)&ah1;
            a2 = *(uint32_t*)&ah2; a3 = *(uint32_t*)&ah3;
        }

        int chunk = 2 * s + cpar;
        #pragma unroll
        for (int t = 0; t < 16; t += 2) {
            int nrow = t * 8 + nrow_lo;
            uint32_t addr = sB_u + (uint32_t)nrow * 256
                          + (uint32_t)((chunk ^ (nrow & 7)) << 4);
            uint32_t b0, b1, b2, b3;
            asm volatile("ldmatrix.sync.aligned.m8n8.x4.shared.b16 {%0,%1,%2,%3}, [%4];"
                         : "=r"(b0), "=r"(b1), "=r"(b2), "=r"(b3) : "r"(addr));
            asm volatile("mma.sync.aligned.m16n8k16.row.col.f32.f16.f16.f32 "
                         "{%0,%1,%2,%3}, {%4,%5,%6,%7}, {%8,%9}, {%0,%1,%2,%3};"
                         : "+f"(d[t][0]), "+f"(d[t][1]), "+f"(d[t][2]), "+f"(d[t][3])
                         : "r"(a0), "r"(a1), "r"(a2), "r"(a3), "r"(b0), "r"(b1));
            asm volatile("mma.sync.aligned.m16n8k16.row.col.f32.f16.f16.f32 "
                         "{%0,%1,%2,%3}, {%4,%5,%6,%7}, {%8,%9}, {%0,%1,%2,%3};"
                         : "+f"(d[t+1][0]), "+f"(d[t+1][1]), "+f"(d[t+1][2]), "+f"(d[t+1][3])
                         : "r"(a0), "r"(a1), "r"(a2), "r"(a3), "r"(b2), "r"(b3));
        }
    }

    unsigned* H0 = (unsigned*)g_h16 + (size_t)(v0 ? r0g : 0) * 64;
    unsigned* H1 = (unsigned*)g_h16 + (size_t)(v1 ? r1g : 0) * 64;
    #pragma unroll
    for (int t = 0; t < 16; t++) {
        int cw = t * 4 + tg;
        if (v0) {
            __half2 o = __floats2half2_rn(d[t][0], d[t][1]);
            H0[cw] = *(unsigned*)&o;
        }
        if (v1) {
            __half2 o = __floats2half2_rn(d[t][2], d[t][3]);
            H1[cw] = *(unsigned*)&o;
        }
    }
}

// ---------------- pull aggregation: one warp/node, 2 edges x 16 lanes ----------------
// out[i] = dinv[i] * sum_e coef_e * h[src_e]  +  dinv[i]^2 * h[i]  +  b ; relu opt
__global__ __launch_bounds__(256) void agg_kernel(const float* __restrict__ bias,
                                                  float* __restrict__ out_ext,
                                                  int n, int do_relu, int dst_is_x2) {
    int gw = (blockIdx.x * blockDim.x + threadIdx.x) >> 5;
    int lane = threadIdx.x & 31;
    if (gw >= n) return;
    int i = gw;
    int half = lane >> 4;    // which of 2 concurrent edges
    int li = lane & 15;      // 16B chunk within the 256B fp16 row

    int off = g_offs[i];
    int end = off + g_hist[i];

    float acc[8];
    #pragma unroll
    for (int j = 0; j < 8; j++) acc[j] = 0.0f;

    #pragma unroll 4
    for (int e0 = off; e0 < end; e0 += 2) {
        int e = e0 + half;
        if (e < end) {
            int2 ed = g_edge[e];
            float c = __int_as_float(ed.y);
            uint4 v = g_h16[(size_t)ed.x * 16 + li];
            __half2* hp = (__half2*)&v;
            float2 f0 = __half22float2(hp[0]);
            float2 f1 = __half22float2(hp[1]);
            float2 f2 = __half22float2(hp[2]);
            float2 f3 = __half22float2(hp[3]);
            acc[0] += c * f0.x; acc[1] += c * f0.y;
            acc[2] += c * f1.x; acc[3] += c * f1.y;
            acc[4] += c * f2.x; acc[5] += c * f2.y;
            acc[6] += c * f3.x; acc[7] += c * f3.y;
        }
    }
    #pragma unroll
    for (int j = 0; j < 8; j++)
        acc[j] += __shfl_xor_sync(0xffffffffu, acc[j], 16);

    float di = g_dinv[i];
    float d2 = di * di;
    uint4 sv = g_h16[(size_t)i * 16 + li];
    __half2* sh = (__half2*)&sv;
    float2 s0 = __half22float2(sh[2 * half + 0]);
    float2 s1 = __half22float2(sh[2 * half + 1]);
    float4 b4 = ((const float4*)bias)[li * 2 + half];

    float4 r;
    r.x = di * acc[4 * half + 0] + d2 * s0.x + b4.x;
    r.y = di * acc[4 * half + 1] + d2 * s0.y + b4.y;
    r.z = di * acc[4 * half + 2] + d2 * s1.x + b4.z;
    r.w = di * acc[4 * half + 3] + d2 * s1.y + b4.w;
    if (do_relu) {
        r.x = fmaxf(r.x, 0.f); r.y = fmaxf(r.y, 0.f);
        r.z = fmaxf(r.z, 0.f); r.w = fmaxf(r.w, 0.f);
    }
    if (dst_is_x2) {
        __half2 o0 = __floats2half2_rn(r.x, r.y);
        __half2 o1 = __floats2half2_rn(r.z, r.w);
        uint2 o; o.x = *(unsigned*)&o0; o.y = *(unsigned*)&o1;
        ((uint2*)g_x16)[(size_t)i * 32 + li * 2 + half] = o;
    } else {
        ((float4*)out_ext)[(size_t)i * 32 + li * 2 + half] = r;
    }
}

// ---------------- launch: two-stream fork/join inside graph capture ----------------
extern "C" void kernel_launch(void* const* d_in, const int* in_sizes, int n_in,
                              void* d_out, int out_size) {
    const float* x  = (const float*)d_in[0];
    const void*  ei = d_in[1];                 // [2, E], int32 OR int64
    const float* ew = (const float*)d_in[2];
    const float* W1 = (const float*)d_in[3];
    const float* b1 = (const float*)d_in[4];
    const float* W2 = (const float*)d_in[5];
    const float* b2 = (const float*)d_in[6];
    float* out = (float*)d_out;

    int n = in_sizes[0] / DIM;   // 100000
    int E = in_sizes[2];         // 3200000

    int nb_n  = (n + 255) / 256;
    int nb_e  = (E + 511) / 512;
    int nb_wn = (n * 32 + 255) / 256;  // one warp per node
    int nb_t  = (n + 127) / 128;       // 782 gemm tiles
    int nb_s  = (n + 1023) / 1024;     // 98

    // side stream + events (host objects; created per call, deterministic)
    cudaStream_t s2;
    cudaEvent_t ev_fork, ev_g1;
    bool forked = (cudaStreamCreateWithFlags(&s2, cudaStreamNonBlocking) == cudaSuccess) &&
                  (cudaEventCreateWithFlags(&ev_fork, cudaEventDisableTiming) == cudaSuccess) &&
                  (cudaEventCreateWithFlags(&ev_g1, cudaEventDisableTiming) == cudaSuccess);

    init_kernel<<<nb_n, 256>>>((const int*)ei, n);

    if (forked) {
        // fork: side branch does wprep + gemm1 (independent of edge preprocessing)
        cudaEventRecord(ev_fork, 0);
        cudaStreamWaitEvent(s2, ev_fork, 0);
        wprep_kernel<<<128, 256, 0, s2>>>(W1, W2);
        gemm_mma_kernel<<<nb_t, 256, 0, s2>>>(x, /*layer2=*/0, n);
        cudaEventRecord(ev_g1, s2);
    } else {
        wprep_kernel<<<128, 256>>>(W1, W2);
        gemm_mma_kernel<<<nb_t, 256>>>(x, /*layer2=*/0, n);
    }

    // main branch: edge preprocessing
    deg_hist_kernel<<<nb_e, 512>>>(ei, ew, E, n);
    scan_all<<<nb_s, 256>>>(n, nb_s);
    scatter_kernel<<<nb_e, 512>>>(ei, ew, E, n);

    if (forked) cudaStreamWaitEvent(0, ev_g1, 0);   // join before agg1

    // layer 1 aggregation, layer 2 gemm + aggregation
    agg_kernel<<<nb_wn, 256>>>(b1, out, n, /*relu=*/1, /*dst_is_x2=*/1);
    gemm_mma_kernel<<<nb_t, 256>>>(x, /*layer2=*/1, n);
    agg_kernel<<<nb_wn, 256>>>(b2, out, n, /*relu=*/0, /*dst_is_x2=*/0);
}

// round 16
// speedup vs baseline: 1.4326x; 1.0715x over previous
#include <cuda_runtime.h>
#include <cuda_fp16.h>
#include <cuda_bf16.h>
#include <stdint.h>

#define N_NODES 100000
#define N_EDGES 3200000
#define DIM 128
#define DIM4 32
#define SCAN_NB 98   // ceil(100000/1024)

// ---------------- scratch (device globals) ----------------
__device__ int                g_is64;
__device__ int                g_done;
__device__ volatile int       g_flag;
__device__ unsigned long long g_dh[N_NODES];   // [40,64) = count, [0,40) = deg 2^-24 fixed pt
__device__ float              g_dinv[N_NODES];
__device__ int                g_hist[N_NODES];
__device__ int                g_offs[N_NODES];
__device__ int                g_cursor[N_NODES];
__device__ int2               g_edge[N_EDGES];  // (src row, (ew*dinv[src]) bits)
__device__ int                g_psum[128];
__device__ int                g_poff[128];
__device__ uint4              g_h16[(size_t)N_NODES * 16];  // fp16 raw h = src @ W, 128 halfs/row
__device__ unsigned           g_x16[(size_t)N_NODES * 64];  // layer-1 output (fp16)
__device__ __half             g_w16a[16384];   // W1^T [n][k] fp16, 16B-chunk XOR swizzled (32KB)
__device__ __half             g_w16b[16384];   // W2^T likewise

// ---------------- edge index readers (dtype-agnostic) ----------------
__device__ __forceinline__ int read_row(const void* ei, int E, int i) {
    if (g_is64) return (int)((const long long*)ei)[i];
    return ((const int*)ei)[i];
}
__device__ __forceinline__ int read_col(const void* ei, int E, int i) {
    if (g_is64) return (int)((const long long*)ei)[(size_t)E + i];
    return ((const int*)ei)[(size_t)E + i];
}

__device__ __forceinline__ uint32_t smem_u32(const void* p) {
    uint32_t a;
    asm("{ .reg .u64 t; cvta.to.shared.u64 t, %1; cvt.u32.u64 %0, t; }" : "=r"(a) : "l"(p));
    return a;
}

// ---------------- init: dh = self-loop; flags; dtype detect ----------------
__global__ void init_kernel(const int* ei_words, int n) {
    int i = blockIdx.x * blockDim.x + threadIdx.x;
    if (i < n) g_dh[i] = (1ULL << 24);
    if (i == 0) {
        g_done = 0;
        g_flag = 0;
        int is64 = 1;
        #pragma unroll 1
        for (int k = 0; k < 64; k++)
            if (ei_words[2 * k + 1] != 0) { is64 = 0; break; }
        g_is64 = is64;
    }
}

// ---------------- W prep: W^T [n][k] fp16, 16B chunks XOR-swizzled by (n&7) ----------------
__global__ void wprep_kernel(const float* __restrict__ W1, const float* __restrict__ W2) {
    int idx = blockIdx.x * blockDim.x + threadIdx.x;   // 32768
    int m = idx >> 14;
    int e = idx & 16383;
    int k = e >> 7, nn = e & 127;                       // read W[k][n], n fastest: coalesced
    float v = m ? W2[e] : W1[e];
    int chunk = (k >> 3) ^ (nn & 7);
    int off = nn * 128 + chunk * 8 + (k & 7);           // in fp16 elements
    (m ? g_w16b : g_w16a)[off] = __float2half_rn(v);
}

// ---------------- deg+hist: ONE u64 reduction per edge ----------------
__global__ void deg_hist_kernel(const void* __restrict__ ei,
                                const float* __restrict__ ew, int E, int n) {
    int i = blockIdx.x * blockDim.x + threadIdx.x;
    if (i < E) {
        int c = read_col(ei, E, i);
        if ((unsigned)c >= (unsigned)n) return;
        unsigned long long fx = (unsigned long long)__float2uint_rn(ew[i] * 16777216.0f);
        atomicAdd(&g_dh[c], (1ULL << 40) | fx);   // no return use -> REDG
    }
}

// ================ scan_all: hist/dinv/offs in ONE kernel (co-resident grid) ================
__global__ __launch_bounds__(256) void scan_all(int n, int nb) {
    __shared__ int wsum[8];
    __shared__ int s_last;
    int b = blockIdx.x, tid = threadIdx.x, lane = tid & 31, wid = tid >> 5;
    int base = b * 1024 + tid * 4;

    int v0 = 0, v1 = 0, v2 = 0, v3 = 0;
    #pragma unroll
    for (int j = 0; j < 4; j++) {
        int i = base + j;
        if (i < n) {
            unsigned long long dh = g_dh[i];
            int cnt = (int)(dh >> 40);
            g_hist[i] = cnt;
            float d = (float)(dh & 0xFFFFFFFFFFULL) * (1.0f / 16777216.0f);
            g_dinv[i] = (d > 0.0f) ? rsqrtf(d) : 0.0f;
            if (j == 0) v0 = cnt; else if (j == 1) v1 = cnt;
            else if (j == 2) v2 = cnt; else v3 = cnt;
        }
    }
    int t = v0 + v1 + v2 + v3;

    int incl = t;
    #pragma unroll
    for (int s = 1; s < 32; s <<= 1) {
        int u = __shfl_up_sync(0xffffffffu, incl, s);
        if (lane >= s) incl += u;
    }
    if (lane == 31) wsum[wid] = incl;
    __syncthreads();
    if (tid == 0) {
        int run = 0;
        #pragma unroll
        for (int j = 0; j < 8; j++) { int u = wsum[j]; wsum[j] = run; run += u; }
        g_psum[b] = run;
        __threadfence();
        int ticket = atomicAdd(&g_done, 1);
        s_last = (ticket == nb - 1);
    }
    __syncthreads();

    if (s_last) {
        if (tid < 32) {
            int carry = 0;
            #pragma unroll
            for (int bb = 0; bb < SCAN_NB; bb += 32) {
                int i = bb + tid;
                int v = (i < SCAN_NB) ? ((volatile int*)g_psum)[i] : 0;
                int inc2 = v;
                #pragma unroll
                for (int st = 1; st < 32; st <<= 1) {
                    int u = __shfl_up_sync(0xffffffffu, inc2, st);
                    if (tid >= st) inc2 += u;
                }
                if (i < SCAN_NB) g_poff[i] = carry + inc2 - v;
                carry += __shfl_sync(0xffffffffu, inc2, 31);
            }
        }
        __syncthreads();
        if (tid == 0) { __threadfence(); g_flag = 1; }
    }
    if (tid == 0) { while (g_flag == 0) { } }   // 98 blocks <= 148 SMs: safe spin
    __syncthreads();

    int excl = g_poff[b] + wsum[wid] + incl - t;
    if (base + 0 < n) { g_offs[base + 0] = excl; g_cursor[base + 0] = excl; } excl += v0;
    if (base + 1 < n) { g_offs[base + 1] = excl; g_cursor[base + 1] = excl; } excl += v1;
    if (base + 2 < n) { g_offs[base + 2] = excl; g_cursor[base + 2] = excl; } excl += v2;
    if (base + 3 < n) { g_offs[base + 3] = excl; g_cursor[base + 3] = excl; }
}

// ---------------- scatter: (row, ew * dinv[row]); streaming store ----------------
__global__ void scatter_kernel(const void* __restrict__ ei,
                               const float* __restrict__ ew, int E, int n) {
    int i = blockIdx.x * blockDim.x + threadIdx.x;
    if (i < E) {
        int r = read_row(ei, E, i);
        int c = read_col(ei, E, i);
        if ((unsigned)r >= (unsigned)n || (unsigned)c >= (unsigned)n) return;
        int pos = atomicAdd(&g_cursor[c], 1);
        if ((unsigned)pos < (unsigned)E) {
            int2 v = make_int2(r, __float_as_int(ew[i] * g_dinv[r]));
            __stcs(&g_edge[pos], v);   // streaming: written once, read once later
        }
    }
}

// ================ tensor-core GEMM: g_h16 = fp16(src @ W) ================
// block = 256 thr (8 warps x 16 rows = 128-row tile); B = W^T[n][k] fp16 in smem (swizzled)
__global__ __launch_bounds__(256) void gemm_mma_kernel(const float* __restrict__ x_ext,
                                                       int layer2, int n) {
    __shared__ __align__(16) __half sB[16384];   // 32KB

    const float* X = x_ext;
    const unsigned* X16 = g_x16;
    const __half* Wimg = layer2 ? g_w16b : g_w16a;

    int tid = threadIdx.x;
    int w = tid >> 5, lane = tid & 31;
    int g = lane >> 2, tg = lane & 3;

    {
        const uint4* src = (const uint4*)Wimg;
        uint4* dst = (uint4*)sB;
        #pragma unroll
        for (int j = 0; j < 8; j++) dst[tid + j * 256] = src[tid + j * 256];
    }
    __syncthreads();
    uint32_t sB_u = smem_u32(sB);

    int r0g = blockIdx.x * 128 + w * 16 + g;
    int r1g = r0g + 8;
    bool v0 = r0g < n, v1 = r1g < n;
    const float* x0 = X + (size_t)(v0 ? r0g : 0) * DIM;
    const float* x1 = X + (size_t)(v1 ? r1g : 0) * DIM;
    const unsigned* q0 = X16 + (size_t)(v0 ? r0g : 0) * 64;
    const unsigned* q1 = X16 + (size_t)(v1 ? r1g : 0) * 64;

    float d[16][4];
    #pragma unroll
    for (int t = 0; t < 16; t++)
        #pragma unroll
        for (int q = 0; q < 4; q++) d[t][q] = 0.0f;

    int half4 = lane >> 3;
    int nrow_lo = (half4 >> 1) * 8 + (lane & 7);
    int cpar = half4 & 1;

    #pragma unroll
    for (int s = 0; s < 8; s++) {
        int k0 = s * 16 + tg * 2;
        uint32_t a0, a1, a2, a3;
        if (layer2) {
            a0 = v0 ? q0[k0 >> 1] : 0u;
            a2 = v0 ? q0[(k0 + 8) >> 1] : 0u;
            a1 = v1 ? q1[k0 >> 1] : 0u;
            a3 = v1 ? q1[(k0 + 8) >> 1] : 0u;
        } else {
            float2 p00 = v0 ? *(const float2*)(x0 + k0)     : make_float2(0.f, 0.f);
            float2 p01 = v0 ? *(const float2*)(x0 + k0 + 8) : make_float2(0.f, 0.f);
            float2 p10 = v1 ? *(const float2*)(x1 + k0)     : make_float2(0.f, 0.f);
            float2 p11 = v1 ? *(const float2*)(x1 + k0 + 8) : make_float2(0.f, 0.f);
            __half2 ah0 = __floats2half2_rn(p00.x, p00.y);
            __half2 ah1 = __floats2half2_rn(p10.x, p10.y);
            __half2 ah2 = __floats2half2_rn(p01.x, p01.y);
            __half2 ah3 = __floats2half2_rn(p11.x, p11.y);
            a0 = *(uint32_t*)&ah0; a1 = *(uint32_t*)&ah1;
            a2 = *(uint32_t*)&ah2; a3 = *(uint32_t*)&ah3;
        }

        int chunk = 2 * s + cpar;
        #pragma unroll
        for (int t = 0; t < 16; t += 2) {
            int nrow = t * 8 + nrow_lo;
            uint32_t addr = sB_u + (uint32_t)nrow * 256
                          + (uint32_t)((chunk ^ (nrow & 7)) << 4);
            uint32_t b0, b1, b2, b3;
            asm volatile("ldmatrix.sync.aligned.m8n8.x4.shared.b16 {%0,%1,%2,%3}, [%4];"
                         : "=r"(b0), "=r"(b1), "=r"(b2), "=r"(b3) : "r"(addr));
            asm volatile("mma.sync.aligned.m16n8k16.row.col.f32.f16.f16.f32 "
                         "{%0,%1,%2,%3}, {%4,%5,%6,%7}, {%8,%9}, {%0,%1,%2,%3};"
                         : "+f"(d[t][0]), "+f"(d[t][1]), "+f"(d[t][2]), "+f"(d[t][3])
                         : "r"(a0), "r"(a1), "r"(a2), "r"(a3), "r"(b0), "r"(b1));
            asm volatile("mma.sync.aligned.m16n8k16.row.col.f32.f16.f16.f32 "
                         "{%0,%1,%2,%3}, {%4,%5,%6,%7}, {%8,%9}, {%0,%1,%2,%3};"
                         : "+f"(d[t+1][0]), "+f"(d[t+1][1]), "+f"(d[t+1][2]), "+f"(d[t+1][3])
                         : "r"(a0), "r"(a1), "r"(a2), "r"(a3), "r"(b2), "r"(b3));
        }
    }

    unsigned* H0 = (unsigned*)g_h16 + (size_t)(v0 ? r0g : 0) * 64;
    unsigned* H1 = (unsigned*)g_h16 + (size_t)(v1 ? r1g : 0) * 64;
    #pragma unroll
    for (int t = 0; t < 16; t++) {
        int cw = t * 4 + tg;
        if (v0) {
            __half2 o = __floats2half2_rn(d[t][0], d[t][1]);
            H0[cw] = *(unsigned*)&o;
        }
        if (v1) {
            __half2 o = __floats2half2_rn(d[t][2], d[t][3]);
            H1[cw] = *(unsigned*)&o;
        }
    }
}

// ---------------- pull aggregation: one warp/node, 2 edges x 16 lanes, deep MLP ----------------
// out[i] = dinv[i] * sum_e coef_e * h[src_e]  +  dinv[i]^2 * h[i]  +  b ; relu opt
__global__ __launch_bounds__(256) void agg_kernel(const float* __restrict__ bias,
                                                  float* __restrict__ out_ext,
                                                  int n, int do_relu, int dst_is_x2) {
    int gw = (blockIdx.x * blockDim.x + threadIdx.x) >> 5;
    int lane = threadIdx.x & 31;
    if (gw >= n) return;
    int i = gw;
    int half = lane >> 4;    // which of 2 concurrent edges
    int li = lane & 15;      // 16B chunk within the 256B fp16 row

    int off = g_offs[i];
    int end = off + g_hist[i];

    float acc[8];
    #pragma unroll
    for (int j = 0; j < 8; j++) acc[j] = 0.0f;

    // prefetched edge record for this lane-half
    int e = off + half;
    int2 ed_next = (e < end) ? g_edge[e] : make_int2(0, 0);

    #pragma unroll 8
    for (int e0 = off; e0 < end; e0 += 2) {
        int2 ed = ed_next;
        bool valid = (e0 + half) < end;
        int e_nx = e0 + 2 + half;
        if (e_nx < end) ed_next = g_edge[e_nx];   // prefetch next iteration's record
        if (valid) {
            float c = __int_as_float(ed.y);
            uint4 v = g_h16[(size_t)ed.x * 16 + li];
            __half2* hp = (__half2*)&v;
            float2 f0 = __half22float2(hp[0]);
            float2 f1 = __half22float2(hp[1]);
            float2 f2 = __half22float2(hp[2]);
            float2 f3 = __half22float2(hp[3]);
            acc[0] += c * f0.x; acc[1] += c * f0.y;
            acc[2] += c * f1.x; acc[3] += c * f1.y;
            acc[4] += c * f2.x; acc[5] += c * f2.y;
            acc[6] += c * f3.x; acc[7] += c * f3.y;
        }
    }
    #pragma unroll
    for (int j = 0; j < 8; j++)
        acc[j] += __shfl_xor_sync(0xffffffffu, acc[j], 16);

    float di = g_dinv[i];
    float d2 = di * di;
    uint4 sv = g_h16[(size_t)i * 16 + li];
    __half2* sh = (__half2*)&sv;
    float2 s0 = __half22float2(sh[2 * half + 0]);
    float2 s1 = __half22float2(sh[2 * half + 1]);
    float4 b4 = ((const float4*)bias)[li * 2 + half];

    float4 r;
    r.x = di * acc[4 * half + 0] + d2 * s0.x + b4.x;
    r.y = di * acc[4 * half + 1] + d2 * s0.y + b4.y;
    r.z = di * acc[4 * half + 2] + d2 * s1.x + b4.z;
    r.w = di * acc[4 * half + 3] + d2 * s1.y + b4.w;
    if (do_relu) {
        r.x = fmaxf(r.x, 0.f); r.y = fmaxf(r.y, 0.f);
        r.z = fmaxf(r.z, 0.f); r.w = fmaxf(r.w, 0.f);
    }
    if (dst_is_x2) {
        __half2 o0 = __floats2half2_rn(r.x, r.y);
        __half2 o1 = __floats2half2_rn(r.z, r.w);
        uint2 o; o.x = *(unsigned*)&o0; o.y = *(unsigned*)&o1;
        ((uint2*)g_x16)[(size_t)i * 32 + li * 2 + half] = o;
    } else {
        ((float4*)out_ext)[(size_t)i * 32 + li * 2 + half] = r;
    }
}

// ---------------- launch: two-stream fork/join inside graph capture ----------------
extern "C" void kernel_launch(void* const* d_in, const int* in_sizes, int n_in,
                              void* d_out, int out_size) {
    const float* x  = (const float*)d_in[0];
    const void*  ei = d_in[1];                 // [2, E], int32 OR int64
    const float* ew = (const float*)d_in[2];
    const float* W1 = (const float*)d_in[3];
    const float* b1 = (const float*)d_in[4];
    const float* W2 = (const float*)d_in[5];
    const float* b2 = (const float*)d_in[6];
    float* out = (float*)d_out;

    int n = in_sizes[0] / DIM;   // 100000
    int E = in_sizes[2];         // 3200000

    int nb_n  = (n + 255) / 256;
    int nb_e  = (E + 511) / 512;
    int nb_wn = (n * 32 + 255) / 256;  // one warp per node
    int nb_t  = (n + 127) / 128;       // 782 gemm tiles
    int nb_s  = (n + 1023) / 1024;     // 98

    // side stream + events (host objects; created per call, deterministic)
    cudaStream_t s2;
    cudaEvent_t ev_fork, ev_g1;
    bool forked = (cudaStreamCreateWithFlags(&s2, cudaStreamNonBlocking) == cudaSuccess) &&
                  (cudaEventCreateWithFlags(&ev_fork, cudaEventDisableTiming) == cudaSuccess) &&
                  (cudaEventCreateWithFlags(&ev_g1, cudaEventDisableTiming) == cudaSuccess);

    init_kernel<<<nb_n, 256>>>((const int*)ei, n);

    if (forked) {
        // fork: side branch does wprep + gemm1 (independent of edge preprocessing)
        cudaEventRecord(ev_fork, 0);
        cudaStreamWaitEvent(s2, ev_fork, 0);
        wprep_kernel<<<128, 256, 0, s2>>>(W1, W2);
        gemm_mma_kernel<<<nb_t, 256, 0, s2>>>(x, /*layer2=*/0, n);
        cudaEventRecord(ev_g1, s2);
    } else {
        wprep_kernel<<<128, 256>>>(W1, W2);
        gemm_mma_kernel<<<nb_t, 256>>>(x, /*layer2=*/0, n);
    }

    // main branch: edge preprocessing
    deg_hist_kernel<<<nb_e, 512>>>(ei, ew, E, n);
    scan_all<<<nb_s, 256>>>(n, nb_s);
    scatter_kernel<<<nb_e, 512>>>(ei, ew, E, n);

    if (forked) cudaStreamWaitEvent(0, ev_g1, 0);   // join before agg1

    // layer 1 aggregation, layer 2 gemm + aggregation
    agg_kernel<<<nb_wn, 256>>>(b1, out, n, /*relu=*/1, /*dst_is_x2=*/1);
    gemm_mma_kernel<<<nb_t, 256>>>(x, /*layer2=*/1, n);
    agg_kernel<<<nb_wn, 256>>>(b2, out, n, /*relu=*/0, /*dst_is_x2=*/0);
}

// round 17
// speedup vs baseline: 1.4460x; 1.0094x over previous
#include <cuda_runtime.h>
#include <cuda_fp16.h>
#include <cuda_bf16.h>
#include <stdint.h>

#define N_NODES 100000
#define N_EDGES 3200000
#define DIM 128
#define DIM4 32
#define SCAN_NB 98   // ceil(100000/1024)

// ---------------- scratch (device globals) ----------------
__device__ int                g_is64;
__device__ int                g_done;
__device__ volatile int       g_flag;
__device__ unsigned long long g_dh[N_NODES];   // [40,64) = count, [0,40) = deg 2^-24 fixed pt
__device__ float              g_dinv[N_NODES];
__device__ int                g_hist[N_NODES];
__device__ int                g_offs[N_NODES];
__device__ int                g_cursor[N_NODES];
__device__ int2               g_edge[N_EDGES];  // (src row, (ew*dinv[src]) bits)
__device__ int                g_psum[128];
__device__ int                g_poff[128];
__device__ uint4              g_h16[(size_t)N_NODES * 16];  // fp16 raw h = src @ W, 128 halfs/row
__device__ unsigned           g_x16[(size_t)N_NODES * 64];  // layer-1 output (fp16)
__device__ __half             g_w16a[16384];   // W1^T [n][k] fp16, 16B-chunk XOR swizzled (32KB)
__device__ __half             g_w16b[16384];   // W2^T likewise

// ---------------- edge index readers (dtype-agnostic, streaming) ----------------
__device__ __forceinline__ int read_row(const void* ei, int E, int i) {
    if (g_is64) return (int)__ldcs(&((const long long*)ei)[i]);
    return __ldcs(&((const int*)ei)[i]);
}
__device__ __forceinline__ int read_col(const void* ei, int E, int i) {
    if (g_is64) return (int)__ldcs(&((const long long*)ei)[(size_t)E + i]);
    return __ldcs(&((const int*)ei)[(size_t)E + i]);
}

__device__ __forceinline__ uint32_t smem_u32(const void* p) {
    uint32_t a;
    asm("{ .reg .u64 t; cvta.to.shared.u64 t, %1; cvt.u32.u64 %0, t; }" : "=r"(a) : "l"(p));
    return a;
}

// ---------------- init: dh = self-loop; flags; dtype detect ----------------
__global__ void init_kernel(const int* ei_words, int n) {
    int i = blockIdx.x * blockDim.x + threadIdx.x;
    if (i < n) g_dh[i] = (1ULL << 24);
    if (i == 0) {
        g_done = 0;
        g_flag = 0;
        int is64 = 1;
        #pragma unroll 1
        for (int k = 0; k < 64; k++)
            if (ei_words[2 * k + 1] != 0) { is64 = 0; break; }
        g_is64 = is64;
    }
}

// ---------------- W prep: W^T [n][k] fp16, 16B chunks XOR-swizzled by (n&7) ----------------
__global__ void wprep_kernel(const float* __restrict__ W1, const float* __restrict__ W2) {
    int idx = blockIdx.x * blockDim.x + threadIdx.x;   // 32768
    int m = idx >> 14;
    int e = idx & 16383;
    int k = e >> 7, nn = e & 127;                       // read W[k][n], n fastest: coalesced
    float v = m ? W2[e] : W1[e];
    int chunk = (k >> 3) ^ (nn & 7);
    int off = nn * 128 + chunk * 8 + (k & 7);           // in fp16 elements
    (m ? g_w16b : g_w16a)[off] = __float2half_rn(v);
}

// ---------------- deg+hist: ONE u64 reduction per edge ----------------
__global__ void deg_hist_kernel(const void* __restrict__ ei,
                                const float* __restrict__ ew, int E, int n) {
    int i = blockIdx.x * blockDim.x + threadIdx.x;
    if (i < E) {
        int c = read_col(ei, E, i);
        if ((unsigned)c >= (unsigned)n) return;
        float w = __ldcs(&ew[i]);
        unsigned long long fx = (unsigned long long)__float2uint_rn(w * 16777216.0f);
        atomicAdd(&g_dh[c], (1ULL << 40) | fx);   // no return use -> REDG
    }
}

// ================ scan_all: hist/dinv/offs in ONE kernel (co-resident grid) ================
__global__ __launch_bounds__(256) void scan_all(int n, int nb) {
    __shared__ int wsum[8];
    __shared__ int s_last;
    int b = blockIdx.x, tid = threadIdx.x, lane = tid & 31, wid = tid >> 5;
    int base = b * 1024 + tid * 4;

    int v0 = 0, v1 = 0, v2 = 0, v3 = 0;
    #pragma unroll
    for (int j = 0; j < 4; j++) {
        int i = base + j;
        if (i < n) {
            unsigned long long dh = g_dh[i];
            int cnt = (int)(dh >> 40);
            g_hist[i] = cnt;
            float d = (float)(dh & 0xFFFFFFFFFFULL) * (1.0f / 16777216.0f);
            g_dinv[i] = (d > 0.0f) ? rsqrtf(d) : 0.0f;
            if (j == 0) v0 = cnt; else if (j == 1) v1 = cnt;
            else if (j == 2) v2 = cnt; else v3 = cnt;
        }
    }
    int t = v0 + v1 + v2 + v3;

    int incl = t;
    #pragma unroll
    for (int s = 1; s < 32; s <<= 1) {
        int u = __shfl_up_sync(0xffffffffu, incl, s);
        if (lane >= s) incl += u;
    }
    if (lane == 31) wsum[wid] = incl;
    __syncthreads();
    if (tid == 0) {
        int run = 0;
        #pragma unroll
        for (int j = 0; j < 8; j++) { int u = wsum[j]; wsum[j] = run; run += u; }
        g_psum[b] = run;
        __threadfence();
        int ticket = atomicAdd(&g_done, 1);
        s_last = (ticket == nb - 1);
    }
    __syncthreads();

    if (s_last) {
        if (tid < 32) {
            int carry = 0;
            #pragma unroll
            for (int bb = 0; bb < SCAN_NB; bb += 32) {
                int i = bb + tid;
                int v = (i < SCAN_NB) ? ((volatile int*)g_psum)[i] : 0;
                int inc2 = v;
                #pragma unroll
                for (int st = 1; st < 32; st <<= 1) {
                    int u = __shfl_up_sync(0xffffffffu, inc2, st);
                    if (tid >= st) inc2 += u;
                }
                if (i < SCAN_NB) g_poff[i] = carry + inc2 - v;
                carry += __shfl_sync(0xffffffffu, inc2, 31);
            }
        }
        __syncthreads();
        if (tid == 0) { __threadfence(); g_flag = 1; }
    }
    if (tid == 0) { while (g_flag == 0) { } }   // 98 blocks <= 148 SMs: safe spin
    __syncthreads();

    int excl = g_poff[b] + wsum[wid] + incl - t;
    if (base + 0 < n) { g_offs[base + 0] = excl; g_cursor[base + 0] = excl; } excl += v0;
    if (base + 1 < n) { g_offs[base + 1] = excl; g_cursor[base + 1] = excl; } excl += v1;
    if (base + 2 < n) { g_offs[base + 2] = excl; g_cursor[base + 2] = excl; } excl += v2;
    if (base + 3 < n) { g_offs[base + 3] = excl; g_cursor[base + 3] = excl; }
}

// ---------------- scatter: (row, ew * dinv[row]); streaming in/out ----------------
__global__ void scatter_kernel(const void* __restrict__ ei,
                               const float* __restrict__ ew, int E, int n) {
    int i = blockIdx.x * blockDim.x + threadIdx.x;
    if (i < E) {
        int r = read_row(ei, E, i);
        int c = read_col(ei, E, i);
        if ((unsigned)r >= (unsigned)n || (unsigned)c >= (unsigned)n) return;
        float w = __ldcs(&ew[i]);
        int pos = atomicAdd(&g_cursor[c], 1);
        if ((unsigned)pos < (unsigned)E) {
            int2 v = make_int2(r, __float_as_int(w * g_dinv[r]));
            __stcs(&g_edge[pos], v);   // streaming: written once, read once later
        }
    }
}

// ================ tensor-core GEMM: g_h16 = fp16(src @ W) ================
// block = 256 thr (8 warps x 16 rows = 128-row tile); B = W^T[n][k] fp16 in smem (swizzled)
__global__ __launch_bounds__(256) void gemm_mma_kernel(const float* __restrict__ x_ext,
                                                       int layer2, int n) {
    __shared__ __align__(16) __half sB[16384];   // 32KB

    const float* X = x_ext;
    const unsigned* X16 = g_x16;
    const __half* Wimg = layer2 ? g_w16b : g_w16a;

    int tid = threadIdx.x;
    int w = tid >> 5, lane = tid & 31;
    int g = lane >> 2, tg = lane & 3;

    {
        const uint4* src = (const uint4*)Wimg;
        uint4* dst = (uint4*)sB;
        #pragma unroll
        for (int j = 0; j < 8; j++) dst[tid + j * 256] = src[tid + j * 256];
    }
    __syncthreads();
    uint32_t sB_u = smem_u32(sB);

    int r0g = blockIdx.x * 128 + w * 16 + g;
    int r1g = r0g + 8;
    bool v0 = r0g < n, v1 = r1g < n;
    const float* x0 = X + (size_t)(v0 ? r0g : 0) * DIM;
    const float* x1 = X + (size_t)(v1 ? r1g : 0) * DIM;
    const unsigned* q0 = X16 + (size_t)(v0 ? r0g : 0) * 64;
    const unsigned* q1 = X16 + (size_t)(v1 ? r1g : 0) * 64;

    float d[16][4];
    #pragma unroll
    for (int t = 0; t < 16; t++)
        #pragma unroll
        for (int q = 0; q < 4; q++) d[t][q] = 0.0f;

    int half4 = lane >> 3;
    int nrow_lo = (half4 >> 1) * 8 + (lane & 7);
    int cpar = half4 & 1;

    #pragma unroll
    for (int s = 0; s < 8; s++) {
        int k0 = s * 16 + tg * 2;
        uint32_t a0, a1, a2, a3;
        if (layer2) {
            a0 = v0 ? q0[k0 >> 1] : 0u;
            a2 = v0 ? q0[(k0 + 8) >> 1] : 0u;
            a1 = v1 ? q1[k0 >> 1] : 0u;
            a3 = v1 ? q1[(k0 + 8) >> 1] : 0u;
        } else {
            float2 p00 = v0 ? *(const float2*)(x0 + k0)     : make_float2(0.f, 0.f);
            float2 p01 = v0 ? *(const float2*)(x0 + k0 + 8) : make_float2(0.f, 0.f);
            float2 p10 = v1 ? *(const float2*)(x1 + k0)     : make_float2(0.f, 0.f);
            float2 p11 = v1 ? *(const float2*)(x1 + k0 + 8) : make_float2(0.f, 0.f);
            __half2 ah0 = __floats2half2_rn(p00.x, p00.y);
            __half2 ah1 = __floats2half2_rn(p10.x, p10.y);
            __half2 ah2 = __floats2half2_rn(p01.x, p01.y);
            __half2 ah3 = __floats2half2_rn(p11.x, p11.y);
            a0 = *(uint32_t*)&ah0; a1 = *(uint32_t*)&ah1;
            a2 = *(uint32_t*)&ah2; a3 = *(uint32_t*)&ah3;
        }

        int chunk = 2 * s + cpar;
        #pragma unroll
        for (int t = 0; t < 16; t += 2) {
            int nrow = t * 8 + nrow_lo;
            uint32_t addr = sB_u + (uint32_t)nrow * 256
                          + (uint32_t)((chunk ^ (nrow & 7)) << 4);
            uint32_t b0, b1, b2, b3;
            asm volatile("ldmatrix.sync.aligned.m8n8.x4.shared.b16 {%0,%1,%2,%3}, [%4];"
                         : "=r"(b0), "=r"(b1), "=r"(b2), "=r"(b3) : "r"(addr));
            asm volatile("mma.sync.aligned.m16n8k16.row.col.f32.f16.f16.f32 "
                         "{%0,%1,%2,%3}, {%4,%5,%6,%7}, {%8,%9}, {%0,%1,%2,%3};"
                         : "+f"(d[t][0]), "+f"(d[t][1]), "+f"(d[t][2]), "+f"(d[t][3])
                         : "r"(a0), "r"(a1), "r"(a2), "r"(a3), "r"(b0), "r"(b1));
            asm volatile("mma.sync.aligned.m16n8k16.row.col.f32.f16.f16.f32 "
                         "{%0,%1,%2,%3}, {%4,%5,%6,%7}, {%8,%9}, {%0,%1,%2,%3};"
                         : "+f"(d[t+1][0]), "+f"(d[t+1][1]), "+f"(d[t+1][2]), "+f"(d[t+1][3])
                         : "r"(a0), "r"(a1), "r"(a2), "r"(a3), "r"(b2), "r"(b3));
        }
    }

    unsigned* H0 = (unsigned*)g_h16 + (size_t)(v0 ? r0g : 0) * 64;
    unsigned* H1 = (unsigned*)g_h16 + (size_t)(v1 ? r1g : 0) * 64;
    #pragma unroll
    for (int t = 0; t < 16; t++) {
        int cw = t * 4 + tg;
        if (v0) {
            __half2 o = __floats2half2_rn(d[t][0], d[t][1]);
            H0[cw] = *(unsigned*)&o;
        }
        if (v1) {
            __half2 o = __floats2half2_rn(d[t][2], d[t][3]);
            H1[cw] = *(unsigned*)&o;
        }
    }
}

// ---------------- pull aggregation: one warp/node, 2 edges x 16 lanes, depth-2 pipeline ----------------
// out[i] = dinv[i] * sum_e coef_e * h[src_e]  +  dinv[i]^2 * h[i]  +  b ; relu opt
__global__ __launch_bounds__(256) void agg_kernel(const float* __restrict__ bias,
                                                  float* __restrict__ out_ext,
                                                  int n, int do_relu, int dst_is_x2) {
    int gw = (blockIdx.x * blockDim.x + threadIdx.x) >> 5;
    int lane = threadIdx.x & 31;
    if (gw >= n) return;
    int i = gw;
    int half = lane >> 4;    // which of 2 concurrent edges
    int li = lane & 15;      // 16B chunk within the 256B fp16 row

    int off = g_offs[i];
    int end = off + g_hist[i];

    float acc[8];
    #pragma unroll
    for (int j = 0; j < 8; j++) acc[j] = 0.0f;

    // depth-2 software pipeline on the edge-record stream
    int e0p = off + half;
    int e1p = off + 2 + half;
    int2 ed0 = (e0p < end) ? g_edge[e0p] : make_int2(0, 0);
    int2 ed1 = (e1p < end) ? g_edge[e1p] : make_int2(0, 0);

    #pragma unroll 16
    for (int e0 = off; e0 < end; e0 += 2) {
        int2 ed = ed0;
        ed0 = ed1;
        int e_nx = e0 + 4 + half;
        if (e_nx < end) ed1 = g_edge[e_nx];   // prefetch two iterations ahead
        if (e0 + half < end) {
            float c = __int_as_float(ed.y);
            uint4 v = g_h16[(size_t)ed.x * 16 + li];
            __half2* hp = (__half2*)&v;
            float2 f0 = __half22float2(hp[0]);
            float2 f1 = __half22float2(hp[1]);
            float2 f2 = __half22float2(hp[2]);
            float2 f3 = __half22float2(hp[3]);
            acc[0] += c * f0.x; acc[1] += c * f0.y;
            acc[2] += c * f1.x; acc[3] += c * f1.y;
            acc[4] += c * f2.x; acc[5] += c * f2.y;
            acc[6] += c * f3.x; acc[7] += c * f3.y;
        }
    }
    #pragma unroll
    for (int j = 0; j < 8; j++)
        acc[j] += __shfl_xor_sync(0xffffffffu, acc[j], 16);

    float di = g_dinv[i];
    float d2 = di * di;
    uint4 sv = g_h16[(size_t)i * 16 + li];
    __half2* sh = (__half2*)&sv;
    float2 s0 = __half22float2(sh[2 * half + 0]);
    float2 s1 = __half22float2(sh[2 * half + 1]);
    float4 b4 = ((const float4*)bias)[li * 2 + half];

    float4 r;
    r.x = di * acc[4 * half + 0] + d2 * s0.x + b4.x;
    r.y = di * acc[4 * half + 1] + d2 * s0.y + b4.y;
    r.z = di * acc[4 * half + 2] + d2 * s1.x + b4.z;
    r.w = di * acc[4 * half + 3] + d2 * s1.y + b4.w;
    if (do_relu) {
        r.x = fmaxf(r.x, 0.f); r.y = fmaxf(r.y, 0.f);
        r.z = fmaxf(r.z, 0.f); r.w = fmaxf(r.w, 0.f);
    }
    if (dst_is_x2) {
        __half2 o0 = __floats2half2_rn(r.x, r.y);
        __half2 o1 = __floats2half2_rn(r.z, r.w);
        uint2 o; o.x = *(unsigned*)&o0; o.y = *(unsigned*)&o1;
        ((uint2*)g_x16)[(size_t)i * 32 + li * 2 + half] = o;
    } else {
        __stcs(&((float4*)out_ext)[(size_t)i * 32 + li * 2 + half], r);
    }
}

// ---------------- launch: two-stream fork/join inside graph capture ----------------
extern "C" void kernel_launch(void* const* d_in, const int* in_sizes, int n_in,
                              void* d_out, int out_size) {
    const float* x  = (const float*)d_in[0];
    const void*  ei = d_in[1];                 // [2, E], int32 OR int64
    const float* ew = (const float*)d_in[2];
    const float* W1 = (const float*)d_in[3];
    const float* b1 = (const float*)d_in[4];
    const float* W2 = (const float*)d_in[5];
    const float* b2 = (const float*)d_in[6];
    float* out = (float*)d_out;

    int n = in_sizes[0] / DIM;   // 100000
    int E = in_sizes[2];         // 3200000

    int nb_n  = (n + 255) / 256;
    int nb_e  = (E + 511) / 512;
    int nb_wn = (n * 32 + 255) / 256;  // one warp per node
    int nb_t  = (n + 127) / 128;       // 782 gemm tiles
    int nb_s  = (n + 1023) / 1024;     // 98

    // side stream + events (host objects; created per call, deterministic)
    cudaStream_t s2;
    cudaEvent_t ev_fork, ev_g1;
    bool forked = (cudaStreamCreateWithFlags(&s2, cudaStreamNonBlocking) == cudaSuccess) &&
                  (cudaEventCreateWithFlags(&ev_fork, cudaEventDisableTiming) == cudaSuccess) &&
                  (cudaEventCreateWithFlags(&ev_g1, cudaEventDisableTiming) == cudaSuccess);

    init_kernel<<<nb_n, 256>>>((const int*)ei, n);

    if (forked) {
        // fork: side branch does wprep + gemm1 (independent of edge preprocessing)
        cudaEventRecord(ev_fork, 0);
        cudaStreamWaitEvent(s2, ev_fork, 0);
        wprep_kernel<<<128, 256, 0, s2>>>(W1, W2);
        gemm_mma_kernel<<<nb_t, 256, 0, s2>>>(x, /*layer2=*/0, n);
        cudaEventRecord(ev_g1, s2);
    } else {
        wprep_kernel<<<128, 256>>>(W1, W2);
        gemm_mma_kernel<<<nb_t, 256>>>(x, /*layer2=*/0, n);
    }

    // main branch: edge preprocessing
    deg_hist_kernel<<<nb_e, 512>>>(ei, ew, E, n);
    scan_all<<<nb_s, 256>>>(n, nb_s);
    scatter_kernel<<<nb_e, 512>>>(ei, ew, E, n);

    if (forked) cudaStreamWaitEvent(0, ev_g1, 0);   // join before agg1

    // layer 1 aggregation, layer 2 gemm + aggregation
    agg_kernel<<<nb_wn, 256>>>(b1, out, n, /*relu=*/1, /*dst_is_x2=*/1);
    gemm_mma_kernel<<<nb_t, 256>>>(x, /*layer2=*/1, n);
    agg_kernel<<<nb_wn, 256>>>(b2, out, n, /*relu=*/0, /*dst_is_x2=*/0);
}